// round 3
// baseline (speedup 1.0000x reference)
#include <cuda_runtime.h>
#include <math.h>

#define Bv 16
#define Sv 2048
#define Ev 256
#define Lv 2
#define NQv 8
#define FFNv 512
#define Cv 2
#define Mv (Bv*Sv)   // 32768 token rows

// Scratch (static device allocations; no cudaMalloc allowed)
__device__ float g_x[Mv*Ev];      // activations      (33.5 MB)
__device__ float g_y[Mv*Ev];      // gemm out scratch (33.5 MB)
__device__ float g_h[Mv*FFNv];    // ffn hidden       (67 MB)

// ---- packed f32x2 helpers (sm_103a; PTX-only path, ptxas never auto-fuses) ----
__device__ __forceinline__ unsigned long long f32x2_pack_dup(float a) {
    unsigned long long r;
    unsigned int ai = __float_as_uint(a);
    asm("mov.b64 %0, {%1, %1};" : "=l"(r) : "r"(ai));
    return r;
}
__device__ __forceinline__ unsigned long long f32x2_fma(unsigned long long a,
                                                        unsigned long long b,
                                                        unsigned long long c) {
    unsigned long long d;
    asm("fma.rn.f32x2 %0, %1, %2, %3;" : "=l"(d) : "l"(a), "l"(b), "l"(c));
    return d;
}
__device__ __forceinline__ float2 f32x2_unpack(unsigned long long v) {
    unsigned int lo, hi;
    asm("mov.b64 {%0, %1}, %2;" : "=r"(lo), "=r"(hi) : "l"(v));
    return make_float2(__uint_as_float(lo), __uint_as_float(hi));
}

// ---------------------------------------------------------------------------
// 1. embedding gather + sinusoidal positional encoding
// ---------------------------------------------------------------------------
__global__ void embed_pos_kernel(const int* __restrict__ tokens,
                                 const float* __restrict__ embed,
                                 float* __restrict__ x) {
    int idx = blockIdx.x * blockDim.x + threadIdx.x;
    if (idx >= Mv * Ev) return;
    int e   = idx & (Ev - 1);
    int row = idx >> 8;
    int s   = row & (Sv - 1);
    int tok = tokens[row];
    float i2 = (float)(e & ~1);
    float d  = expf(i2 * (-9.210340371976184f / 256.0f));  // 10000^{-i/dim}
    float arg = (float)s * d;
    float pe = (e & 1) ? cosf(arg) : sinf(arg);
    x[idx] = embed[tok * Ev + e] + pe;
}

// ---------------------------------------------------------------------------
// 2. Tiled SGEMM with packed f32x2 FMA: C[M,N] = op(A)[M,K] @ B[K,N] + bias
//    MODE 0: op(A)=A           MODE 1: op(A)=cos(A + theta[k & 63])
//    Block tile 128x128, K-chunk 16, thread tile 8x8 (as 8x4 f32x2), 256 thr.
// ---------------------------------------------------------------------------
template<int MODE>
__global__ void __launch_bounds__(256, 2)
sgemm128(const float* __restrict__ A, const float* __restrict__ Bm,
         const float* __restrict__ bias, const float* __restrict__ theta,
         float* __restrict__ Cm, int M, int N, int K) {
    __shared__ float As[16][128];   // transposed: As[k][m]
    __shared__ float Bs[16][128];

    const int t    = threadIdx.x;
    const int tx   = t & 15;        // 0..15  -> col group
    const int ty   = t >> 4;        // 0..15  -> row group
    const int row0 = blockIdx.y * 128;
    const int col0 = blockIdx.x * 128;

    unsigned long long acc[8][4];   // 8 rows x 4 packed col-pairs
#pragma unroll
    for (int i = 0; i < 8; i++)
#pragma unroll
        for (int j = 0; j < 4; j++) acc[i][j] = 0ull;   // {0.f,0.f}

    for (int k0 = 0; k0 < K; k0 += 16) {
        // load A tile (128 rows x 16 k), apply transform, store transposed
#pragma unroll
        for (int p = 0; p < 2; p++) {
            int idx = p * 256 + t;
            int r   = idx >> 2;           // 0..127
            int kq  = idx & 3;            // 0..3  (float4 within 16-k row)
            float4 a = *(const float4*)(A + (size_t)(row0 + r) * K + k0 + kq * 4);
            if (MODE == 1) {
                int kb = k0 + kq * 4;
                a.x = cosf(a.x + theta[(kb + 0) & 63]);
                a.y = cosf(a.y + theta[(kb + 1) & 63]);
                a.z = cosf(a.z + theta[(kb + 2) & 63]);
                a.w = cosf(a.w + theta[(kb + 3) & 63]);
            }
            As[kq * 4 + 0][r] = a.x;
            As[kq * 4 + 1][r] = a.y;
            As[kq * 4 + 2][r] = a.z;
            As[kq * 4 + 3][r] = a.w;
        }
        // load B tile (16 k x 128 cols)
#pragma unroll
        for (int p = 0; p < 2; p++) {
            int idx = p * 256 + t;
            int kr  = idx >> 5;           // 0..15
            int cq  = idx & 31;           // float4 col group
            float4 b = *(const float4*)(Bm + (size_t)(k0 + kr) * N + col0 + cq * 4);
            *(float4*)&Bs[kr][cq * 4] = b;
        }
        __syncthreads();

#pragma unroll
        for (int kk = 0; kk < 16; kk++) {
            float4 a0 = *(const float4*)&As[kk][ty * 8];
            float4 a1 = *(const float4*)&As[kk][ty * 8 + 4];
            // B pairs come packed for free out of the LDS.128 register quads
            ulonglong2 bq0 = *(const ulonglong2*)&Bs[kk][tx * 8];
            ulonglong2 bq1 = *(const ulonglong2*)&Bs[kk][tx * 8 + 4];
            unsigned long long bp[4] = {bq0.x, bq0.y, bq1.x, bq1.y};
            float av[8] = {a0.x, a0.y, a0.z, a0.w, a1.x, a1.y, a1.z, a1.w};
#pragma unroll
            for (int i = 0; i < 8; i++) {
                unsigned long long ap = f32x2_pack_dup(av[i]);
#pragma unroll
                for (int j = 0; j < 4; j++)
                    acc[i][j] = f32x2_fma(ap, bp[j], acc[i][j]);
            }
        }
        __syncthreads();
    }

    // epilogue: + bias, store
    float bj[8];
#pragma unroll
    for (int j = 0; j < 8; j++) bj[j] = bias[col0 + tx * 8 + j];
#pragma unroll
    for (int i = 0; i < 8; i++) {
        int row = row0 + ty * 8 + i;
        float2 c0 = f32x2_unpack(acc[i][0]);
        float2 c1 = f32x2_unpack(acc[i][1]);
        float2 c2 = f32x2_unpack(acc[i][2]);
        float2 c3 = f32x2_unpack(acc[i][3]);
        float4 o0 = make_float4(c0.x + bj[0], c0.y + bj[1],
                                c1.x + bj[2], c1.y + bj[3]);
        float4 o1 = make_float4(c2.x + bj[4], c2.y + bj[5],
                                c3.x + bj[6], c3.y + bj[7]);
        *(float4*)(Cm + (size_t)row * N + col0 + tx * 8)     = o0;
        *(float4*)(Cm + (size_t)row * N + col0 + tx * 8 + 4) = o1;
    }
}

// ---------------------------------------------------------------------------
// 3. residual + LayerNorm: out = LN(x + y) * g + b    (warp per row, E=256)
// ---------------------------------------------------------------------------
__global__ void ln_resid_kernel(const float* __restrict__ x,
                                const float* __restrict__ y,
                                const float* __restrict__ g,
                                const float* __restrict__ b,
                                float* __restrict__ out) {
    int warp = (blockIdx.x * blockDim.x + threadIdx.x) >> 5;
    int lane = threadIdx.x & 31;
    if (warp >= Mv) return;
    const float4* xr = (const float4*)(x + (size_t)warp * Ev);
    const float4* yr = (const float4*)(y + (size_t)warp * Ev);
    float4 x0 = xr[lane], x1 = xr[lane + 32];
    float4 y0 = yr[lane], y1 = yr[lane + 32];
    float v[8] = {x0.x + y0.x, x0.y + y0.y, x0.z + y0.z, x0.w + y0.w,
                  x1.x + y1.x, x1.y + y1.y, x1.z + y1.z, x1.w + y1.w};
    float sum = 0.f;
#pragma unroll
    for (int i = 0; i < 8; i++) sum += v[i];
#pragma unroll
    for (int o = 16; o; o >>= 1) sum += __shfl_xor_sync(0xffffffffu, sum, o);
    float m = sum * (1.0f / Ev);
    float vs = 0.f;
#pragma unroll
    for (int i = 0; i < 8; i++) { float d = v[i] - m; vs += d * d; }
#pragma unroll
    for (int o = 16; o; o >>= 1) vs += __shfl_xor_sync(0xffffffffu, vs, o);
    float inv = rsqrtf(vs * (1.0f / Ev) + 1e-5f);

    const float4* gr = (const float4*)g;
    const float4* br = (const float4*)b;
    float4 g0 = gr[lane], g1 = gr[lane + 32];
    float4 b0 = br[lane], b1 = br[lane + 32];
    float4 o0, o1;
    o0.x = (v[0] - m) * inv * g0.x + b0.x;
    o0.y = (v[1] - m) * inv * g0.y + b0.y;
    o0.z = (v[2] - m) * inv * g0.z + b0.z;
    o0.w = (v[3] - m) * inv * g0.w + b0.w;
    o1.x = (v[4] - m) * inv * g1.x + b1.x;
    o1.y = (v[5] - m) * inv * g1.y + b1.y;
    o1.z = (v[6] - m) * inv * g1.z + b1.z;
    o1.w = (v[7] - m) * inv * g1.w + b1.w;
    float4* orow = (float4*)(out + (size_t)warp * Ev);
    orow[lane] = o0; orow[lane + 32] = o1;
}

// ---------------------------------------------------------------------------
// 4. FFN hidden: h = relu( (cos(x[:, :8]) * cos(theta)) @ W1 + b1 )
//    block handles 8 rows, 256 threads
// ---------------------------------------------------------------------------
__global__ void ffn_h_kernel(const float* __restrict__ x,
                             const float* __restrict__ ffn_theta,
                             const float* __restrict__ W1,
                             const float* __restrict__ b1,
                             float* __restrict__ h) {
    int row0 = blockIdx.x * 8;
    int t = threadIdx.x;
    __shared__ float qs[8][NQv];
    if (t < 64) {
        int m = t >> 3, n = t & 7;
        qs[m][n] = cosf(x[(size_t)(row0 + m) * Ev + n]) * cosf(ffn_theta[n]);
    }
    __syncthreads();
#pragma unroll
    for (int fo = 0; fo < FFNv; fo += 256) {
        int f = fo + t;
        float w[NQv];
#pragma unroll
        for (int n = 0; n < NQv; n++) w[n] = W1[n * FFNv + f];
        float bb = b1[f];
#pragma unroll
        for (int m = 0; m < 8; m++) {
            float acc = bb;
#pragma unroll
            for (int n = 0; n < NQv; n++) acc = fmaf(qs[m][n], w[n], acc);
            h[(size_t)(row0 + m) * FFNv + f] = fmaxf(acc, 0.f);
        }
    }
}

// ---------------------------------------------------------------------------
// 5. pooled mean + classifier
// ---------------------------------------------------------------------------
#define POOL_SPLIT 32
__global__ void pool1_kernel(const float* __restrict__ x, float* __restrict__ part) {
    int b = blockIdx.x, sp = blockIdx.y;
    int e = threadIdx.x;
    size_t base = ((size_t)b * Sv + (size_t)sp * (Sv / POOL_SPLIT)) * Ev + e;
    float s = 0.f;
#pragma unroll 4
    for (int i = 0; i < Sv / POOL_SPLIT; i++) s += x[base + (size_t)i * Ev];
    part[((size_t)b * POOL_SPLIT + sp) * Ev + e] = s;
}

__global__ void pool2_kernel(const float* __restrict__ part,
                             const float* __restrict__ cls_w,
                             const float* __restrict__ cls_b,
                             float* __restrict__ out) {
    int b = blockIdx.x;
    int e = threadIdx.x;
    float s = 0.f;
#pragma unroll
    for (int i = 0; i < POOL_SPLIT; i++) s += part[((size_t)b * POOL_SPLIT + i) * Ev + e];
    s *= (1.0f / Sv);
    __shared__ float red[Ev];
#pragma unroll
    for (int c = 0; c < Cv; c++) {
        red[e] = s * cls_w[e * Cv + c];
        __syncthreads();
        for (int o = 128; o; o >>= 1) {
            if (e < o) red[e] += red[e + o];
            __syncthreads();
        }
        if (e == 0) out[b * Cv + c] = red[0] + cls_b[c];
        __syncthreads();
    }
}

// ---------------------------------------------------------------------------
extern "C" void kernel_launch(void* const* d_in, const int* in_sizes, int n_in,
                              void* d_out, int out_size) {
    const int*   tokens     = (const int*)  d_in[0];
    const float* embed      = (const float*)d_in[1];
    const float* attn_theta = (const float*)d_in[2];
    const float* combine_w  = (const float*)d_in[3];
    const float* combine_b  = (const float*)d_in[4];
    const float* ffn_theta  = (const float*)d_in[5];
    const float* lin1_w     = (const float*)d_in[6];
    const float* lin1_b     = (const float*)d_in[7];
    const float* lin2_w     = (const float*)d_in[8];
    const float* lin2_b     = (const float*)d_in[9];
    const float* ln1_g      = (const float*)d_in[10];
    const float* ln1_b      = (const float*)d_in[11];
    const float* ln2_g      = (const float*)d_in[12];
    const float* ln2_b      = (const float*)d_in[13];
    const float* cls_w      = (const float*)d_in[14];
    const float* cls_b      = (const float*)d_in[15];
    float* out = (float*)d_out;

    float *x, *y, *h;
    cudaGetSymbolAddress((void**)&x, g_x);
    cudaGetSymbolAddress((void**)&y, g_y);
    cudaGetSymbolAddress((void**)&h, g_h);

    // 1. embed + positional encoding
    embed_pos_kernel<<<(Mv * Ev + 255) / 256, 256>>>(tokens, embed, x);

    dim3 gemmGridE(Ev / 128, Mv / 128);   // attn / lin2 GEMM (N=256)

    for (int l = 0; l < Lv; l++) {
        // attention: y = cos(x + theta) @ combine_w + combine_b
        sgemm128<1><<<gemmGridE, 256>>>(x, combine_w + (size_t)l * Ev * Ev,
                                        combine_b + l * Ev, attn_theta + l * 64,
                                        y, Mv, Ev, Ev);
        // x = LN(x + y)
        ln_resid_kernel<<<Mv / 8, 256>>>(x, y, ln1_g + l * Ev, ln1_b + l * Ev, x);
        // h = relu(q @ lin1_w + b1)
        ffn_h_kernel<<<Mv / 8, 256>>>(x, ffn_theta + l * NQv,
                                      lin1_w + (size_t)l * NQv * FFNv,
                                      lin1_b + l * FFNv, h);
        // y = h @ lin2_w + b2
        sgemm128<0><<<gemmGridE, 256>>>(h, lin2_w + (size_t)l * FFNv * Ev,
                                        lin2_b + l * Ev, (const float*)0,
                                        y, Mv, Ev, FFNv);
        // x = LN(x + y)
        ln_resid_kernel<<<Mv / 8, 256>>>(x, y, ln2_g + l * Ev, ln2_b + l * Ev, x);
    }

    // pooled mean + classifier
    dim3 pgrid(Bv, POOL_SPLIT);
    pool1_kernel<<<pgrid, Ev>>>(x, y);
    pool2_kernel<<<Bv, Ev>>>(y, cls_w, cls_b, out);
}

// round 15
// speedup vs baseline: 1.1666x; 1.1666x over previous
#include <cuda_runtime.h>
#include <cuda_bf16.h>
#include <mma.h>
#include <math.h>
#include <stdint.h>

using namespace nvcuda;

#define Bv 16
#define Sv 2048
#define Ev 256
#define Lv 2
#define NQv 8
#define FFNv 512
#define Cv 2
#define Mv (Bv*Sv)   // 32768 token rows

// Scratch (static device allocations; no cudaMalloc allowed)
__device__ float          g_x[Mv*Ev];      // activations
__device__ float          g_y[Mv*Ev];      // gemm out scratch
__device__ float          g_h[Mv*FFNv];    // ffn hidden
__device__ __nv_bfloat16  g_bth[Ev*FFNv];  // transposed B, bf16 hi (max 256x512)
__device__ __nv_bfloat16  g_btl[Ev*FFNv];  // transposed B, bf16 lo

// ---------------------------------------------------------------------------
// 1. embedding gather + sinusoidal positional encoding
// ---------------------------------------------------------------------------
__global__ void embed_pos_kernel(const int* __restrict__ tokens,
                                 const float* __restrict__ embed,
                                 float* __restrict__ x) {
    int idx = blockIdx.x * blockDim.x + threadIdx.x;
    if (idx >= Mv * Ev) return;
    int e   = idx & (Ev - 1);
    int row = idx >> 8;
    int s   = row & (Sv - 1);
    int tok = tokens[row];
    float i2 = (float)(e & ~1);
    float d  = expf(i2 * (-9.210340371976184f / 256.0f));
    float arg = (float)s * d;
    float pe = (e & 1) ? cosf(arg) : sinf(arg);
    x[idx] = embed[tok * Ev + e] + pe;
}

// ---------------------------------------------------------------------------
// 2a. prep: transpose B [K,N=256] -> Bt [N,K], split into bf16 hi/lo
// ---------------------------------------------------------------------------
__global__ void prep_bt_kernel(const float* __restrict__ B,
                               __nv_bfloat16* __restrict__ bth,
                               __nv_bfloat16* __restrict__ btl, int K) {
    int idx = blockIdx.x * 256 + threadIdx.x;
    if (idx >= K * Ev) return;
    int k = idx >> 8, n = idx & 255;
    float v = B[idx];
    __nv_bfloat16 hi = __float2bfloat16(v);
    __nv_bfloat16 lo = __float2bfloat16(v - __bfloat162float(hi));
    bth[(size_t)n * K + k] = hi;
    btl[(size_t)n * K + k] = lo;
}

// ---------------------------------------------------------------------------
// 2b. wmma bf16 GEMM (3-term split): C[M,256] = op(A)[M,K] @ B[K,256] + bias
//     MODE 0: op(A)=A     MODE 1: op(A)=cos(A + theta[k & 63])
//     CTA tile 128x128, 8 warps (2x4), warp tile 64x32, K-chunk 32.
// ---------------------------------------------------------------------------
#define PADA 48                         // bf16 elems per smem row (32 data + 16 pad)
#define SA_ELE (128*PADA)               // 6144 bf16 = 12288 B per tile
#define SMEM_TOT (128*132*4)            // 67584 B (epilogue buffer is the max)

template<int MODE>
__global__ void __launch_bounds__(256)
wmma_gemm(const float* __restrict__ A,
          const __nv_bfloat16* __restrict__ bth,
          const __nv_bfloat16* __restrict__ btl,
          const float* __restrict__ bias, const float* __restrict__ theta,
          float* __restrict__ C, int K) {
    extern __shared__ char smem[];
    __nv_bfloat16* sAh = (__nv_bfloat16*)smem;            // [128][PADA]
    __nv_bfloat16* sAl = sAh + SA_ELE;
    __nv_bfloat16* sBh = sAl + SA_ELE;
    __nv_bfloat16* sBl = sBh + SA_ELE;

    const int t      = threadIdx.x;
    const int w      = t >> 5;
    const int warp_m = w & 1;           // 0..1 -> 64-row band
    const int warp_n = w >> 1;          // 0..3 -> 32-col band
    const int row0   = blockIdx.y * 128;
    const int col0   = blockIdx.x * 128;

    wmma::fragment<wmma::accumulator, 16, 16, 16, float> acc[4][2];
#pragma unroll
    for (int mi = 0; mi < 4; mi++)
#pragma unroll
        for (int ni = 0; ni < 2; ni++) wmma::fill_fragment(acc[mi][ni], 0.0f);

    const int r    = t >> 1;            // 0..127 (tile row)
    const int half = t & 1;             // which 16-wide k half

    for (int k0 = 0; k0 < K; k0 += 32) {
        // ---- A tile: 16 floats -> transform -> bf16 hi/lo ----
        {
            const float4* arow = (const float4*)(A + (size_t)(row0 + r) * K + k0 + half * 16);
            __nv_bfloat16* dAh = sAh + r * PADA + half * 16;
            __nv_bfloat16* dAl = sAl + r * PADA + half * 16;
#pragma unroll
            for (int q = 0; q < 4; q++) {
                float4 v = arow[q];
                if (MODE == 1) {
                    int kb = k0 + half * 16 + q * 4;
                    v.x = cosf(v.x + theta[(kb + 0) & 63]);
                    v.y = cosf(v.y + theta[(kb + 1) & 63]);
                    v.z = cosf(v.z + theta[(kb + 2) & 63]);
                    v.w = cosf(v.w + theta[(kb + 3) & 63]);
                }
                float vv[4] = {v.x, v.y, v.z, v.w};
#pragma unroll
                for (int j = 0; j < 4; j++) {
                    __nv_bfloat16 hi = __float2bfloat16(vv[j]);
                    __nv_bfloat16 lo = __float2bfloat16(vv[j] - __bfloat162float(hi));
                    dAh[q * 4 + j] = hi;
                    dAl[q * 4 + j] = lo;
                }
            }
        }
        // ---- B tile: copy 16 bf16 (hi & lo) for row col0+r ----
        {
            const uint4* bh = (const uint4*)(bth + (size_t)(col0 + r) * K + k0 + half * 16);
            const uint4* bl = (const uint4*)(btl + (size_t)(col0 + r) * K + k0 + half * 16);
            uint4* dBh = (uint4*)(sBh + r * PADA + half * 16);
            uint4* dBl = (uint4*)(sBl + r * PADA + half * 16);
            dBh[0] = bh[0]; dBh[1] = bh[1];
            dBl[0] = bl[0]; dBl[1] = bl[1];
        }
        __syncthreads();

#pragma unroll
        for (int kk = 0; kk < 2; kk++) {
            wmma::fragment<wmma::matrix_a, 16, 16, 16, __nv_bfloat16, wmma::row_major> ah[4], al[4];
            wmma::fragment<wmma::matrix_b, 16, 16, 16, __nv_bfloat16, wmma::col_major> bh[2], bl[2];
#pragma unroll
            for (int mi = 0; mi < 4; mi++) {
                const __nv_bfloat16* ap = sAh + (warp_m * 64 + mi * 16) * PADA + kk * 16;
                const __nv_bfloat16* lp = sAl + (warp_m * 64 + mi * 16) * PADA + kk * 16;
                wmma::load_matrix_sync(ah[mi], ap, PADA);
                wmma::load_matrix_sync(al[mi], lp, PADA);
            }
#pragma unroll
            for (int ni = 0; ni < 2; ni++) {
                const __nv_bfloat16* bp = sBh + (warp_n * 32 + ni * 16) * PADA + kk * 16;
                const __nv_bfloat16* lp = sBl + (warp_n * 32 + ni * 16) * PADA + kk * 16;
                wmma::load_matrix_sync(bh[ni], bp, PADA);
                wmma::load_matrix_sync(bl[ni], lp, PADA);
            }
#pragma unroll
            for (int mi = 0; mi < 4; mi++)
#pragma unroll
                for (int ni = 0; ni < 2; ni++) {
                    wmma::mma_sync(acc[mi][ni], ah[mi], bh[ni], acc[mi][ni]);
                    wmma::mma_sync(acc[mi][ni], ah[mi], bl[ni], acc[mi][ni]);
                    wmma::mma_sync(acc[mi][ni], al[mi], bh[ni], acc[mi][ni]);
                }
        }
        __syncthreads();
    }

    // ---- epilogue: fragments -> smem (ld 132) -> +bias -> gmem ----
    float* sOut = (float*)smem;
#pragma unroll
    for (int mi = 0; mi < 4; mi++)
#pragma unroll
        for (int ni = 0; ni < 2; ni++)
            wmma::store_matrix_sync(sOut + (warp_m * 64 + mi * 16) * 132
                                         + warp_n * 32 + ni * 16,
                                    acc[mi][ni], 132, wmma::mem_row_major);
    __syncthreads();
    for (int i = t; i < 128 * 32; i += 256) {
        int rr = i >> 5;
        int cg = (i & 31) * 4;
        float4 v = *(float4*)(sOut + rr * 132 + cg);
        v.x += bias[col0 + cg + 0];
        v.y += bias[col0 + cg + 1];
        v.z += bias[col0 + cg + 2];
        v.w += bias[col0 + cg + 3];
        *(float4*)(C + (size_t)(row0 + rr) * 256 + col0 + cg) = v;
    }
}

// ---------------------------------------------------------------------------
// 3. residual + LayerNorm: out = LN(x + y) * g + b    (warp per row, E=256)
// ---------------------------------------------------------------------------
__global__ void ln_resid_kernel(const float* __restrict__ x,
                                const float* __restrict__ y,
                                const float* __restrict__ g,
                                const float* __restrict__ b,
                                float* __restrict__ out) {
    int warp = (blockIdx.x * blockDim.x + threadIdx.x) >> 5;
    int lane = threadIdx.x & 31;
    if (warp >= Mv) return;
    const float4* xr = (const float4*)(x + (size_t)warp * Ev);
    const float4* yr = (const float4*)(y + (size_t)warp * Ev);
    float4 x0 = xr[lane], x1 = xr[lane + 32];
    float4 y0 = yr[lane], y1 = yr[lane + 32];
    float v[8] = {x0.x + y0.x, x0.y + y0.y, x0.z + y0.z, x0.w + y0.w,
                  x1.x + y1.x, x1.y + y1.y, x1.z + y1.z, x1.w + y1.w};
    float sum = 0.f;
#pragma unroll
    for (int i = 0; i < 8; i++) sum += v[i];
#pragma unroll
    for (int o = 16; o; o >>= 1) sum += __shfl_xor_sync(0xffffffffu, sum, o);
    float m = sum * (1.0f / Ev);
    float vs = 0.f;
#pragma unroll
    for (int i = 0; i < 8; i++) { float d = v[i] - m; vs += d * d; }
#pragma unroll
    for (int o = 16; o; o >>= 1) vs += __shfl_xor_sync(0xffffffffu, vs, o);
    float inv = rsqrtf(vs * (1.0f / Ev) + 1e-5f);

    const float4* gr = (const float4*)g;
    const float4* br = (const float4*)b;
    float4 g0 = gr[lane], g1 = gr[lane + 32];
    float4 b0 = br[lane], b1 = br[lane + 32];
    float4 o0, o1;
    o0.x = (v[0] - m) * inv * g0.x + b0.x;
    o0.y = (v[1] - m) * inv * g0.y + b0.y;
    o0.z = (v[2] - m) * inv * g0.z + b0.z;
    o0.w = (v[3] - m) * inv * g0.w + b0.w;
    o1.x = (v[4] - m) * inv * g1.x + b1.x;
    o1.y = (v[5] - m) * inv * g1.y + b1.y;
    o1.z = (v[6] - m) * inv * g1.z + b1.z;
    o1.w = (v[7] - m) * inv * g1.w + b1.w;
    float4* orow = (float4*)(out + (size_t)warp * Ev);
    orow[lane] = o0; orow[lane + 32] = o1;
}

// ---------------------------------------------------------------------------
// 4. FFN hidden: h = relu( (cos(x[:, :8]) * cos(theta)) @ W1 + b1 )
// ---------------------------------------------------------------------------
__global__ void ffn_h_kernel(const float* __restrict__ x,
                             const float* __restrict__ ffn_theta,
                             const float* __restrict__ W1,
                             const float* __restrict__ b1,
                             float* __restrict__ h) {
    int row0 = blockIdx.x * 8;
    int t = threadIdx.x;
    __shared__ float qs[8][NQv];
    if (t < 64) {
        int m = t >> 3, n = t & 7;
        qs[m][n] = cosf(x[(size_t)(row0 + m) * Ev + n]) * cosf(ffn_theta[n]);
    }
    __syncthreads();
#pragma unroll
    for (int fo = 0; fo < FFNv; fo += 256) {
        int f = fo + t;
        float w[NQv];
#pragma unroll
        for (int n = 0; n < NQv; n++) w[n] = W1[n * FFNv + f];
        float bb = b1[f];
#pragma unroll
        for (int m = 0; m < 8; m++) {
            float acc = bb;
#pragma unroll
            for (int n = 0; n < NQv; n++) acc = fmaf(qs[m][n], w[n], acc);
            h[(size_t)(row0 + m) * FFNv + f] = fmaxf(acc, 0.f);
        }
    }
}

// ---------------------------------------------------------------------------
// 5. pooled mean + classifier
// ---------------------------------------------------------------------------
#define POOL_SPLIT 32
__global__ void pool1_kernel(const float* __restrict__ x, float* __restrict__ part) {
    int b = blockIdx.x, sp = blockIdx.y;
    int e = threadIdx.x;
    size_t base = ((size_t)b * Sv + (size_t)sp * (Sv / POOL_SPLIT)) * Ev + e;
    float s = 0.f;
#pragma unroll 4
    for (int i = 0; i < Sv / POOL_SPLIT; i++) s += x[base + (size_t)i * Ev];
    part[((size_t)b * POOL_SPLIT + sp) * Ev + e] = s;
}

__global__ void pool2_kernel(const float* __restrict__ part,
                             const float* __restrict__ cls_w,
                             const float* __restrict__ cls_b,
                             float* __restrict__ out) {
    int b = blockIdx.x;
    int e = threadIdx.x;
    float s = 0.f;
#pragma unroll
    for (int i = 0; i < POOL_SPLIT; i++) s += part[((size_t)b * POOL_SPLIT + i) * Ev + e];
    s *= (1.0f / Sv);
    __shared__ float red[Ev];
#pragma unroll
    for (int c = 0; c < Cv; c++) {
        red[e] = s * cls_w[e * Cv + c];
        __syncthreads();
        for (int o = 128; o; o >>= 1) {
            if (e < o) red[e] += red[e + o];
            __syncthreads();
        }
        if (e == 0) out[b * Cv + c] = red[0] + cls_b[c];
        __syncthreads();
    }
}

// ---------------------------------------------------------------------------
extern "C" void kernel_launch(void* const* d_in, const int* in_sizes, int n_in,
                              void* d_out, int out_size) {
    const int*   tokens     = (const int*)  d_in[0];
    const float* embed      = (const float*)d_in[1];
    const float* attn_theta = (const float*)d_in[2];
    const float* combine_w  = (const float*)d_in[3];
    const float* combine_b  = (const float*)d_in[4];
    const float* ffn_theta  = (const float*)d_in[5];
    const float* lin1_w     = (const float*)d_in[6];
    const float* lin1_b     = (const float*)d_in[7];
    const float* lin2_w     = (const float*)d_in[8];
    const float* lin2_b     = (const float*)d_in[9];
    const float* ln1_g      = (const float*)d_in[10];
    const float* ln1_b      = (const float*)d_in[11];
    const float* ln2_g      = (const float*)d_in[12];
    const float* ln2_b      = (const float*)d_in[13];
    const float* cls_w      = (const float*)d_in[14];
    const float* cls_b      = (const float*)d_in[15];
    float* out = (float*)d_out;

    float *x, *y, *h;
    __nv_bfloat16 *bth, *btl;
    cudaGetSymbolAddress((void**)&x, g_x);
    cudaGetSymbolAddress((void**)&y, g_y);
    cudaGetSymbolAddress((void**)&h, g_h);
    cudaGetSymbolAddress((void**)&bth, g_bth);
    cudaGetSymbolAddress((void**)&btl, g_btl);

    cudaFuncSetAttribute(wmma_gemm<0>, cudaFuncAttributeMaxDynamicSharedMemorySize, SMEM_TOT);
    cudaFuncSetAttribute(wmma_gemm<1>, cudaFuncAttributeMaxDynamicSharedMemorySize, SMEM_TOT);

    embed_pos_kernel<<<(Mv * Ev + 255) / 256, 256>>>(tokens, embed, x);

    dim3 ggrid(Ev / 128, Mv / 128);   // (2, 256)

    for (int l = 0; l < Lv; l++) {
        // attention: y = cos(x + theta) @ combine_w + combine_b
        prep_bt_kernel<<<(Ev * Ev + 255) / 256, 256>>>(
            combine_w + (size_t)l * Ev * Ev, bth, btl, Ev);
        wmma_gemm<1><<<ggrid, 256, SMEM_TOT>>>(
            x, bth, btl, combine_b + l * Ev, attn_theta + l * 64, y, Ev);
        ln_resid_kernel<<<Mv / 8, 256>>>(x, y, ln1_g + l * Ev, ln1_b + l * Ev, x);

        // h = relu(q @ lin1_w + b1)
        ffn_h_kernel<<<Mv / 8, 256>>>(x, ffn_theta + l * NQv,
                                      lin1_w + (size_t)l * NQv * FFNv,
                                      lin1_b + l * FFNv, h);
        // y = h @ lin2_w + b2
        prep_bt_kernel<<<(FFNv * Ev + 255) / 256, 256>>>(
            lin2_w + (size_t)l * FFNv * Ev, bth, btl, FFNv);
        wmma_gemm<0><<<ggrid, 256, SMEM_TOT>>>(
            h, bth, btl, lin2_b + l * Ev, (const float*)0, y, FFNv);
        ln_resid_kernel<<<Mv / 8, 256>>>(x, y, ln2_g + l * Ev, ln2_b + l * Ev, x);
    }

    dim3 pgrid(Bv, POOL_SPLIT);
    pool1_kernel<<<pgrid, Ev>>>(x, y);
    pool2_kernel<<<Bv, Ev>>>(y, cls_w, cls_b, out);
}

// round 16
// speedup vs baseline: 2.1307x; 1.8264x over previous
#include <cuda_runtime.h>
#include <cuda_fp16.h>
#include <mma.h>
#include <math.h>
#include <stdint.h>

using namespace nvcuda;

#define Bv 16
#define Sv 2048
#define Ev 256
#define Lv 2
#define NQv 8
#define FFNv 512
#define Cv 2
#define Mv (Bv*Sv)   // 32768 token rows

// Scratch (static device allocations; no cudaMalloc allowed)
__device__ float  g_x[Mv*Ev];      // activations (in-place updated)
__device__ float  g_h[Mv*FFNv];    // ffn hidden + pool scratch
__device__ __half g_bth[Ev*FFNv];  // transposed B, fp16 (max 256x512)

// ---------------------------------------------------------------------------
// 1. embedding gather + sinusoidal positional encoding
// ---------------------------------------------------------------------------
__global__ void embed_pos_kernel(const int* __restrict__ tokens,
                                 const float* __restrict__ embed,
                                 float* __restrict__ x) {
    int idx = blockIdx.x * blockDim.x + threadIdx.x;
    if (idx >= Mv * Ev) return;
    int e   = idx & (Ev - 1);
    int row = idx >> 8;
    int s   = row & (Sv - 1);
    int tok = tokens[row];
    float i2 = (float)(e & ~1);
    float d  = expf(i2 * (-9.210340371976184f / 256.0f));
    float arg = (float)s * d;
    float pe = (e & 1) ? cosf(arg) : sinf(arg);
    x[idx] = embed[tok * Ev + e] + pe;
}

// ---------------------------------------------------------------------------
// 2a. prep: transpose B [K,N=256] -> Bt [N,K], round to fp16
// ---------------------------------------------------------------------------
__global__ void prep_bt_kernel(const float* __restrict__ B,
                               __half* __restrict__ bth, int K) {
    int idx = blockIdx.x * 256 + threadIdx.x;
    if (idx >= K * Ev) return;
    int k = idx >> 8, n = idx & 255;
    bth[(size_t)n * K + k] = __float2half_rn(B[idx]);
}

// ---------------------------------------------------------------------------
// 2b. wmma fp16 GEMM (2-term: A split exact, B rounded) + fused residual+LN.
//     xnew[M,256] = LN( xres + op(A)@B + bias ) * g + b
//     MODE 0: op(A)=A     MODE 1: op(A)=cos(A + theta[k & 63])
//     CTA tile 128x256 (full row), 512 threads = 16 warps, warp tile 32x64.
// ---------------------------------------------------------------------------
#define PADH 40                      // halfs per smem row (32 data + 8 pad)
#define SA_H (128*PADH)              // 5120 halfs
#define LDC  260
#define SMEM_TOT (128*LDC*4)         // 133120 B (epilogue fp32 buffer is max)

template<int MODE>
__global__ void __launch_bounds__(512)
gemm_ln(const float* __restrict__ A, const __half* __restrict__ Bt,
        const float* __restrict__ bias, const float* __restrict__ theta,
        const float* __restrict__ lng, const float* __restrict__ lnb,
        const float* __restrict__ xres, float* __restrict__ Cout, int K) {
    extern __shared__ char smem[];
    __half* sAh = (__half*)smem;               // [128][PADH]
    __half* sAl = sAh + SA_H;                  // [128][PADH]
    __half* sBh = sAl + SA_H;                  // [256][PADH]

    const int t      = threadIdx.x;
    const int w      = t >> 5;
    const int lane   = t & 31;
    const int warp_m = w & 3;                  // 4 bands of 32 rows
    const int warp_n = w >> 2;                 // 4 bands of 64 cols
    const int row0   = blockIdx.x * 128;

    wmma::fragment<wmma::accumulator, 16, 16, 16, float> acc[2][4];
#pragma unroll
    for (int mi = 0; mi < 2; mi++)
#pragma unroll
        for (int ni = 0; ni < 4; ni++) wmma::fill_fragment(acc[mi][ni], 0.0f);

    const int rA = t >> 2, qA = t & 3;         // A: row 0..127, 8-float group
    const int rB = t >> 1, qB = t & 1;         // B: row 0..255, 16-half group

    for (int k0 = 0; k0 < K; k0 += 32) {
        // ---- A tile: 8 floats -> transform -> fp16 hi + exact lo residual ----
        {
            const float4* ar = (const float4*)(A + (size_t)(row0 + rA) * K + k0 + qA * 8);
            __half hh[8], hl[8];
#pragma unroll
            for (int p = 0; p < 2; p++) {
                float4 v = ar[p];
                float vv[4] = {v.x, v.y, v.z, v.w};
#pragma unroll
                for (int j = 0; j < 4; j++) {
                    float f = vv[j];
                    if (MODE == 1) f = cosf(f + theta[(k0 + qA * 8 + p * 4 + j) & 63]);
                    __half hi = __float2half_rn(f);
                    hh[p * 4 + j] = hi;
                    hl[p * 4 + j] = __float2half_rn(f - __half2float(hi));
                }
            }
            *(uint4*)(sAh + rA * PADH + qA * 8) = *(uint4*)hh;
            *(uint4*)(sAl + rA * PADH + qA * 8) = *(uint4*)hl;
        }
        // ---- B tile: 16 halfs (2 x uint4) for row rB ----
        {
            const uint4* bs = (const uint4*)(Bt + (size_t)rB * K + k0 + qB * 16);
            uint4* bd = (uint4*)(sBh + rB * PADH + qB * 16);
            bd[0] = bs[0]; bd[1] = bs[1];
        }
        __syncthreads();

#pragma unroll
        for (int kk = 0; kk < 2; kk++) {
            wmma::fragment<wmma::matrix_a, 16, 16, 16, __half, wmma::row_major> ah[2], al[2];
#pragma unroll
            for (int mi = 0; mi < 2; mi++) {
                const __half* ap = sAh + (warp_m * 32 + mi * 16) * PADH + kk * 16;
                const __half* lp = sAl + (warp_m * 32 + mi * 16) * PADH + kk * 16;
                wmma::load_matrix_sync(ah[mi], ap, PADH);
                wmma::load_matrix_sync(al[mi], lp, PADH);
            }
#pragma unroll
            for (int ni = 0; ni < 4; ni++) {
                wmma::fragment<wmma::matrix_b, 16, 16, 16, __half, wmma::col_major> bh;
                wmma::load_matrix_sync(bh, sBh + (warp_n * 64 + ni * 16) * PADH + kk * 16, PADH);
#pragma unroll
                for (int mi = 0; mi < 2; mi++) {
                    wmma::mma_sync(acc[mi][ni], ah[mi], bh, acc[mi][ni]);
                    wmma::mma_sync(acc[mi][ni], al[mi], bh, acc[mi][ni]);
                }
            }
        }
        __syncthreads();
    }

    // ---- epilogue: acc -> smem, then fused bias + residual + LayerNorm ----
    float* sOut = (float*)smem;
#pragma unroll
    for (int mi = 0; mi < 2; mi++)
#pragma unroll
        for (int ni = 0; ni < 4; ni++)
            wmma::store_matrix_sync(sOut + (warp_m * 32 + mi * 16) * LDC
                                         + warp_n * 64 + ni * 16,
                                    acc[mi][ni], LDC, wmma::mem_row_major);
    __syncthreads();

    // warp w handles rows w*8 .. w*8+7; lane owns 8 contiguous cols
#pragma unroll
    for (int rr8 = 0; rr8 < 8; rr8++) {
        int row = w * 8 + rr8;
        int grow = row0 + row;
        int c0 = lane * 8;
        float* rp = sOut + row * LDC + c0;
        float4 a0 = *(float4*)rp;
        float4 a1 = *(float4*)(rp + 4);
        const float4* xr = (const float4*)(xres + (size_t)grow * Ev + c0);
        float4 x0 = xr[0], x1 = xr[1];
        const float4* br = (const float4*)(bias + c0);
        float4 b0 = br[0], b1 = br[1];
        float v[8] = {a0.x + x0.x + b0.x, a0.y + x0.y + b0.y,
                      a0.z + x0.z + b0.z, a0.w + x0.w + b0.w,
                      a1.x + x1.x + b1.x, a1.y + x1.y + b1.y,
                      a1.z + x1.z + b1.z, a1.w + x1.w + b1.w};
        float s = 0.f, sq = 0.f;
#pragma unroll
        for (int j = 0; j < 8; j++) { s += v[j]; sq += v[j] * v[j]; }
#pragma unroll
        for (int o = 16; o; o >>= 1) {
            s  += __shfl_xor_sync(0xffffffffu, s,  o);
            sq += __shfl_xor_sync(0xffffffffu, sq, o);
        }
        float m   = s * (1.0f / Ev);
        float var = sq * (1.0f / Ev) - m * m;
        float inv = rsqrtf(var + 1e-5f);
        const float4* gr = (const float4*)(lng + c0);
        const float4* bbr = (const float4*)(lnb + c0);
        float4 g0 = gr[0], g1 = gr[1];
        float4 lb0 = bbr[0], lb1 = bbr[1];
        float4 o0, o1;
        o0.x = (v[0] - m) * inv * g0.x + lb0.x;
        o0.y = (v[1] - m) * inv * g0.y + lb0.y;
        o0.z = (v[2] - m) * inv * g0.z + lb0.z;
        o0.w = (v[3] - m) * inv * g0.w + lb0.w;
        o1.x = (v[4] - m) * inv * g1.x + lb1.x;
        o1.y = (v[5] - m) * inv * g1.y + lb1.y;
        o1.z = (v[6] - m) * inv * g1.z + lb1.z;
        o1.w = (v[7] - m) * inv * g1.w + lb1.w;
        float4* op = (float4*)(Cout + (size_t)grow * Ev + c0);
        op[0] = o0; op[1] = o1;
    }
}

// ---------------------------------------------------------------------------
// 3. FFN hidden: h = relu( (cos(x[:, :8]) * cos(theta)) @ W1 + b1 )
// ---------------------------------------------------------------------------
__global__ void ffn_h_kernel(const float* __restrict__ x,
                             const float* __restrict__ ffn_theta,
                             const float* __restrict__ W1,
                             const float* __restrict__ b1,
                             float* __restrict__ h) {
    int row0 = blockIdx.x * 8;
    int t = threadIdx.x;
    __shared__ float qs[8][NQv];
    if (t < 64) {
        int m = t >> 3, n = t & 7;
        qs[m][n] = cosf(x[(size_t)(row0 + m) * Ev + n]) * cosf(ffn_theta[n]);
    }
    __syncthreads();
#pragma unroll
    for (int fo = 0; fo < FFNv; fo += 256) {
        int f = fo + t;
        float w[NQv];
#pragma unroll
        for (int n = 0; n < NQv; n++) w[n] = W1[n * FFNv + f];
        float bb = b1[f];
#pragma unroll
        for (int m = 0; m < 8; m++) {
            float acc = bb;
#pragma unroll
            for (int n = 0; n < NQv; n++) acc = fmaf(qs[m][n], w[n], acc);
            h[(size_t)(row0 + m) * FFNv + f] = fmaxf(acc, 0.f);
        }
    }
}

// ---------------------------------------------------------------------------
// 4. pooled mean + classifier
// ---------------------------------------------------------------------------
#define POOL_SPLIT 32
__global__ void pool1_kernel(const float* __restrict__ x, float* __restrict__ part) {
    int b = blockIdx.x, sp = blockIdx.y;
    int e = threadIdx.x;
    size_t base = ((size_t)b * Sv + (size_t)sp * (Sv / POOL_SPLIT)) * Ev + e;
    float s = 0.f;
#pragma unroll 4
    for (int i = 0; i < Sv / POOL_SPLIT; i++) s += x[base + (size_t)i * Ev];
    part[((size_t)b * POOL_SPLIT + sp) * Ev + e] = s;
}

__global__ void pool2_kernel(const float* __restrict__ part,
                             const float* __restrict__ cls_w,
                             const float* __restrict__ cls_b,
                             float* __restrict__ out) {
    int b = blockIdx.x;
    int e = threadIdx.x;
    float s = 0.f;
#pragma unroll
    for (int i = 0; i < POOL_SPLIT; i++) s += part[((size_t)b * POOL_SPLIT + i) * Ev + e];
    s *= (1.0f / Sv);
    __shared__ float red[Ev];
#pragma unroll
    for (int c = 0; c < Cv; c++) {
        red[e] = s * cls_w[e * Cv + c];
        __syncthreads();
        for (int o = 128; o; o >>= 1) {
            if (e < o) red[e] += red[e + o];
            __syncthreads();
        }
        if (e == 0) out[b * Cv + c] = red[0] + cls_b[c];
        __syncthreads();
    }
}

// ---------------------------------------------------------------------------
extern "C" void kernel_launch(void* const* d_in, const int* in_sizes, int n_in,
                              void* d_out, int out_size) {
    const int*   tokens     = (const int*)  d_in[0];
    const float* embed      = (const float*)d_in[1];
    const float* attn_theta = (const float*)d_in[2];
    const float* combine_w  = (const float*)d_in[3];
    const float* combine_b  = (const float*)d_in[4];
    const float* ffn_theta  = (const float*)d_in[5];
    const float* lin1_w     = (const float*)d_in[6];
    const float* lin1_b     = (const float*)d_in[7];
    const float* lin2_w     = (const float*)d_in[8];
    const float* lin2_b     = (const float*)d_in[9];
    const float* ln1_g      = (const float*)d_in[10];
    const float* ln1_b      = (const float*)d_in[11];
    const float* ln2_g      = (const float*)d_in[12];
    const float* ln2_b      = (const float*)d_in[13];
    const float* cls_w      = (const float*)d_in[14];
    const float* cls_b      = (const float*)d_in[15];
    float* out = (float*)d_out;

    float *x, *h;
    __half *bth;
    cudaGetSymbolAddress((void**)&x, g_x);
    cudaGetSymbolAddress((void**)&h, g_h);
    cudaGetSymbolAddress((void**)&bth, g_bth);

    cudaFuncSetAttribute(gemm_ln<0>, cudaFuncAttributeMaxDynamicSharedMemorySize, SMEM_TOT);
    cudaFuncSetAttribute(gemm_ln<1>, cudaFuncAttributeMaxDynamicSharedMemorySize, SMEM_TOT);

    embed_pos_kernel<<<(Mv * Ev + 255) / 256, 256>>>(tokens, embed, x);

    for (int l = 0; l < Lv; l++) {
        // x = LN( x + cos(x+theta)@combine_w + combine_b ) * g1 + b1
        prep_bt_kernel<<<(Ev * Ev + 255) / 256, 256>>>(
            combine_w + (size_t)l * Ev * Ev, bth, Ev);
        gemm_ln<1><<<Mv / 128, 512, SMEM_TOT>>>(
            x, bth, combine_b + l * Ev, attn_theta + l * 64,
            ln1_g + l * Ev, ln1_b + l * Ev, x, x, Ev);

        // h = relu(q @ lin1_w + b1)
        ffn_h_kernel<<<Mv / 8, 256>>>(x, ffn_theta + l * NQv,
                                      lin1_w + (size_t)l * NQv * FFNv,
                                      lin1_b + l * FFNv, h);
        // x = LN( x + h@lin2_w + lin2_b ) * g2 + b2
        prep_bt_kernel<<<(FFNv * Ev + 255) / 256, 256>>>(
            lin2_w + (size_t)l * FFNv * Ev, bth, FFNv);
        gemm_ln<0><<<Mv / 128, 512, SMEM_TOT>>>(
            h, bth, lin2_b + l * Ev, (const float*)0,
            ln2_g + l * Ev, ln2_b + l * Ev, x, x, FFNv);
    }

    dim3 pgrid(Bv, POOL_SPLIT);
    pool1_kernel<<<pgrid, Ev>>>(x, h);
    pool2_kernel<<<Bv, Ev>>>(h, cls_w, cls_b, out);
}